// round 1
// baseline (speedup 1.0000x reference)
#include <cuda_runtime.h>
#include <cuda_bf16.h>
#include <cstdint>

#define N_ROWS 8192
#define D_DIM  512
#define ROW_TILE 128
#define COL_SPLIT 2
#define COLS_PER_CTA (N_ROWS / COL_SPLIT)   // 4096
#define CHUNK 64
#define APITCH 520   // 512 + 8 bf16 pad -> 1040B row stride, conflict-free ldmatrix
#define MAIN_THREADS 256

// scratch (static device allocations are allowed; cudaMalloc is not)
__device__ __align__(16) __nv_bfloat16 g_fn[N_ROWS * D_DIM];
__device__ int   g_lab[N_ROWS];
__device__ float g_tot[N_ROWS];
__device__ float g_same[N_ROWS];

__device__ __forceinline__ float fast_ex2(float x) {
    float y;
    asm("ex2.approx.ftz.f32 %0, %1;" : "=f"(y) : "f"(x));
    return y;
}

__device__ __forceinline__ void ldsm_x4(uint32_t &r0, uint32_t &r1, uint32_t &r2, uint32_t &r3,
                                        uint32_t addr) {
    asm volatile("ldmatrix.sync.aligned.m8n8.x4.shared.b16 {%0,%1,%2,%3}, [%4];"
                 : "=r"(r0), "=r"(r1), "=r"(r2), "=r"(r3) : "r"(addr));
}

__device__ __forceinline__ void mma_16816(float c[4],
                                          uint32_t a0, uint32_t a1, uint32_t a2, uint32_t a3,
                                          uint32_t b0, uint32_t b1) {
    asm volatile("mma.sync.aligned.m16n8k16.row.col.f32.bf16.bf16.f32 "
                 "{%0,%1,%2,%3}, {%4,%5,%6,%7}, {%8,%9}, {%0,%1,%2,%3};"
                 : "+f"(c[0]), "+f"(c[1]), "+f"(c[2]), "+f"(c[3])
                 : "r"(a0), "r"(a1), "r"(a2), "r"(a3), "r"(b0), "r"(b1));
}

// ---------------------------------------------------------------------------
// Labels: robust to int64 vs int32 delivery. If int64 (little-endian), every
// odd 32-bit word is 0 (labels are 0..15). P(false positive for int32) ~ 0.
// ---------------------------------------------------------------------------
__global__ void convert_labels_kernel(const int* __restrict__ raw) {
    int tid = threadIdx.x;
    int bad = 0;
    for (int i = tid; i < N_ROWS / 2; i += blockDim.x)
        if (raw[2 * i + 1] != 0) bad = 1;
    int any = __syncthreads_or(bad);
    if (any) {  // int32 input
        for (int r = tid; r < N_ROWS; r += blockDim.x) g_lab[r] = raw[r];
    } else {    // int64 input
        for (int r = tid; r < N_ROWS; r += blockDim.x) g_lab[r] = raw[2 * r];
    }
}

// ---------------------------------------------------------------------------
// Normalize rows, fold sqrt(log2(e)/T) into both operands, convert to bf16.
// Also zero the per-row accumulators (graph replays need re-zeroing).
// ---------------------------------------------------------------------------
__global__ void prep_kernel(const float* __restrict__ feat) {
    int r = blockIdx.x;
    int tid = threadIdx.x;   // 128 threads, 4 floats each
    float4 v = reinterpret_cast<const float4*>(feat + (size_t)r * D_DIM)[tid];
    float ss = v.x * v.x + v.y * v.y + v.z * v.z + v.w * v.w;
    #pragma unroll
    for (int o = 16; o; o >>= 1) ss += __shfl_xor_sync(0xffffffffu, ss, o);
    __shared__ float wsum[4];
    if ((tid & 31) == 0) wsum[tid >> 5] = ss;
    __syncthreads();
    float tot = wsum[0] + wsum[1] + wsum[2] + wsum[3];
    float norm = fmaxf(sqrtf(tot), 1e-12f);
    const float SC = sqrtf(1.44269504088896340f / 0.07f);  // sqrt(log2(e)/T), const-folded
    float s = SC / norm;
    __nv_bfloat16* out = g_fn + (size_t)r * D_DIM + tid * 4;
    out[0] = __float2bfloat16(v.x * s);
    out[1] = __float2bfloat16(v.y * s);
    out[2] = __float2bfloat16(v.z * s);
    out[3] = __float2bfloat16(v.w * s);
    if (tid == 0) { g_tot[r] = 0.f; g_same[r] = 0.f; }
}

// ---------------------------------------------------------------------------
// Fused GEMM + exp + masked row sums.
// Grid: 128 CTAs = (8192/128 row blocks) x 2 column halves.
// CTA: A tile (128 x 512) resident in smem; loop 64-col B chunks.
// Warps: 4 row-groups x 2 col-groups, each warp 32 rows x 32 cols.
// ---------------------------------------------------------------------------
__global__ void __launch_bounds__(MAIN_THREADS, 1)
contrastive_main_kernel() {
    extern __shared__ char smem_raw[];
    __nv_bfloat16* As = reinterpret_cast<__nv_bfloat16*>(smem_raw);
    __nv_bfloat16* Bs = As + ROW_TILE * APITCH;
    int* Ls = reinterpret_cast<int*>(Bs + CHUNK * APITCH);

    int tid  = threadIdx.x;
    int lane = tid & 31;
    int warp = tid >> 5;
    int rowGroup = warp >> 1;   // 0..3
    int colGroup = warp & 1;    // 0..1

    int rowBase = (blockIdx.x >> 1) * ROW_TILE;
    int jStart  = (blockIdx.x & 1) * COLS_PER_CTA;

    // Load A tile (once per CTA), 16B per thread-iteration, coalesced.
    for (int i = tid; i < ROW_TILE * (D_DIM / 8); i += MAIN_THREADS) {
        int r = i >> 6;
        int u = i & 63;
        *reinterpret_cast<uint4*>(As + r * APITCH + u * 8) =
            *reinterpret_cast<const uint4*>(g_fn + (size_t)(rowBase + r) * D_DIM + u * 8);
    }

    int qr = lane >> 2;          // 0..7   (fragment row within 8)
    int qc = (lane & 3) << 1;    // 0,2,4,6 (fragment col pair)

    // This thread's 4 row labels: index k = mt*2+h -> row = rg*32 + mt*16 + h*8 + qr
    int rl[4];
    #pragma unroll
    for (int k = 0; k < 4; k++)
        rl[k] = g_lab[rowBase + rowGroup * 32 + (k >> 1) * 16 + (k & 1) * 8 + qr];

    // ldmatrix base addresses (per-thread). x4 lane->matrix mapping: m = lane/8.
    int m   = lane >> 3;
    int rim = lane & 7;
    uint32_t aBase[2], bBase[2];
    {
        int rowoff = (m & 1) * 8;      // a0,a1 = k0-7 halves rows r/r+8; a2,a3 = k8-15
        int koff   = (m >> 1) * 8;
        #pragma unroll
        for (int mt = 0; mt < 2; mt++) {
            int row = rowGroup * 32 + mt * 16 + rim + rowoff;
            aBase[mt] = (uint32_t)__cvta_generic_to_shared(As + row * APITCH + koff);
        }
        int noff  = (m >> 1) * 8;      // m0,m1 -> nfrag even; m2,m3 -> nfrag odd
        int koff2 = (m & 1) * 8;       // m0,m2 -> b0 (k0-7); m1,m3 -> b1 (k8-15)
        #pragma unroll
        for (int nh = 0; nh < 2; nh++) {
            int row = colGroup * 32 + nh * 16 + rim + noff;
            bBase[nh] = (uint32_t)__cvta_generic_to_shared(Bs + row * APITCH + koff2);
        }
    }

    float tot[4] = {0.f, 0.f, 0.f, 0.f};
    float sme[4] = {0.f, 0.f, 0.f, 0.f};

    for (int jb = 0; jb < COLS_PER_CTA; jb += CHUNK) {
        int jbase = jStart + jb;
        __syncthreads();  // previous chunk's Bs/Ls reads done (also covers A store, iter 0)
        for (int i = tid; i < CHUNK * (D_DIM / 8); i += MAIN_THREADS) {
            int r = i >> 6;
            int u = i & 63;
            *reinterpret_cast<uint4*>(Bs + r * APITCH + u * 8) =
                *reinterpret_cast<const uint4*>(g_fn + (size_t)(jbase + r) * D_DIM + u * 8);
        }
        if (tid < CHUNK) Ls[tid] = g_lab[jbase + tid];
        __syncthreads();

        float acc[2][4][4];
        #pragma unroll
        for (int mt = 0; mt < 2; mt++)
            #pragma unroll
            for (int nf = 0; nf < 4; nf++)
                #pragma unroll
                for (int e = 0; e < 4; e++) acc[mt][nf][e] = 0.f;

        #pragma unroll 4
        for (int ks = 0; ks < D_DIM / 16; ks++) {
            uint32_t koffB = (uint32_t)ks * 32;   // 16 bf16 = 32 bytes per k-step
            uint32_t a[2][4];
            ldsm_x4(a[0][0], a[0][1], a[0][2], a[0][3], aBase[0] + koffB);
            ldsm_x4(a[1][0], a[1][1], a[1][2], a[1][3], aBase[1] + koffB);
            uint32_t b[4][2];
            {
                uint32_t r0, r1, r2, r3;
                ldsm_x4(r0, r1, r2, r3, bBase[0] + koffB);
                b[0][0] = r0; b[0][1] = r1; b[1][0] = r2; b[1][1] = r3;
                ldsm_x4(r0, r1, r2, r3, bBase[1] + koffB);
                b[2][0] = r0; b[2][1] = r1; b[3][0] = r2; b[3][1] = r3;
            }
            #pragma unroll
            for (int mt = 0; mt < 2; mt++)
                #pragma unroll
                for (int nf = 0; nf < 4; nf++)
                    mma_16816(acc[mt][nf], a[mt][0], a[mt][1], a[mt][2], a[mt][3],
                              b[nf][0], b[nf][1]);
        }

        // Epilogue: exp (arg already scaled by log2(e)/T) + masked accumulation.
        #pragma unroll
        for (int mt = 0; mt < 2; mt++) {
            #pragma unroll
            for (int nf = 0; nf < 4; nf++) {
                int cb  = colGroup * 32 + nf * 8 + qc;
                int j0  = jbase + cb;
                int lj0 = Ls[cb], lj1 = Ls[cb + 1];
                #pragma unroll
                for (int h = 0; h < 2; h++) {
                    int gi = rowBase + rowGroup * 32 + mt * 16 + h * 8 + qr;
                    int li = rl[mt * 2 + h];
                    float e0 = fast_ex2(acc[mt][nf][2 * h]);
                    float e1 = fast_ex2(acc[mt][nf][2 * h + 1]);
                    if (gi != j0)     { tot[mt * 2 + h] += e0; if (li == lj0) sme[mt * 2 + h] += e0; }
                    if (gi != j0 + 1) { tot[mt * 2 + h] += e1; if (li == lj1) sme[mt * 2 + h] += e1; }
                }
            }
        }
    }

    // Quad-lane reduce (lanes 4q..4q+3 hold the same rows), then atomics.
    #pragma unroll
    for (int k = 0; k < 4; k++) {
        float t = tot[k], s = sme[k];
        t += __shfl_xor_sync(0xffffffffu, t, 1);
        t += __shfl_xor_sync(0xffffffffu, t, 2);
        s += __shfl_xor_sync(0xffffffffu, s, 1);
        s += __shfl_xor_sync(0xffffffffu, s, 2);
        if ((lane & 3) == 0) {
            int row = rowBase + rowGroup * 32 + (k >> 1) * 16 + (k & 1) * 8 + qr;
            atomicAdd(&g_tot[row], t);
            atomicAdd(&g_same[row], s);
        }
    }
}

// ---------------------------------------------------------------------------
// Final: loss = -mean(log((same + 1e-7*total)/total)), zero if non-finite.
// ---------------------------------------------------------------------------
__global__ void finalize_kernel(float* __restrict__ out) {
    int tid = threadIdx.x;  // 256
    float acc = 0.f;
    for (int r = tid; r < N_ROWS; r += 256) {
        float t = g_tot[r];
        float p = g_same[r] + 1e-7f * t;
        acc += logf(p / t);
    }
    #pragma unroll
    for (int o = 16; o; o >>= 1) acc += __shfl_xor_sync(0xffffffffu, acc, o);
    __shared__ float ws[8];
    if ((tid & 31) == 0) ws[tid >> 5] = acc;
    __syncthreads();
    if (tid == 0) {
        float s = 0.f;
        #pragma unroll
        for (int w = 0; w < 8; w++) s += ws[w];
        float loss = -s / (float)N_ROWS;
        if (!isfinite(loss)) loss = 0.f;
        out[0] = loss;
    }
}

extern "C" void kernel_launch(void* const* d_in, const int* in_sizes, int n_in,
                              void* d_out, int out_size) {
    (void)in_sizes; (void)n_in; (void)out_size;
    const float* feat   = (const float*)d_in[0];
    const int*   labraw = (const int*)d_in[1];
    float* out = (float*)d_out;

    size_t smem = (size_t)(ROW_TILE + CHUNK) * APITCH * sizeof(__nv_bfloat16)
                + CHUNK * sizeof(int);   // 199,936 bytes
    cudaFuncSetAttribute(contrastive_main_kernel,
                         cudaFuncAttributeMaxDynamicSharedMemorySize, (int)smem);

    convert_labels_kernel<<<1, 256>>>(labraw);
    prep_kernel<<<N_ROWS, 128>>>(feat);
    contrastive_main_kernel<<<(N_ROWS / ROW_TILE) * COL_SPLIT, MAIN_THREADS, smem>>>();
    finalize_kernel<<<1, 256>>>(out);
}

// round 3
// speedup vs baseline: 2.0400x; 2.0400x over previous
#include <cuda_runtime.h>
#include <cuda_bf16.h>
#include <cstdint>

#define N_ROWS 8192
#define D_DIM  512
#define ROW_TILE 128
#define COL_SPLIT 2
#define COLS_PER_CTA (N_ROWS / COL_SPLIT)   // 4096
#define CHUNK 64
#define NCHUNKS (COLS_PER_CTA / CHUNK)      // 32
#define P 528                                // int8 row pitch: 512 + 16 (conflict-free ldmatrix)
#define BSZ (CHUNK * P)                      // 33792
#define THREADS 256

// smem layout (bytes)
#define SM_A 0                               // 128 * 528 = 67584
#define SM_B (ROW_TILE * P)                  // 2 * 33792 = 67584
#define SM_L (SM_B + 2 * BSZ)                // 2 * 256 label bytes
#define SM_Q (SM_L + 512)                    // 2 * 256 qscale bytes
#define SMEM_TOTAL (SM_Q + 512)              // 136704 - 512 = 136192

// static device scratch (cudaMalloc forbidden)
__device__ __align__(16) unsigned char g_q[N_ROWS * D_DIM];  // int8 quantized rows
__device__ float g_qs[N_ROWS];   // per-row dequant scale * sqrt(log2e/T)
__device__ int   g_lab[N_ROWS];
__device__ float g_tot[N_ROWS];
__device__ float g_same[N_ROWS];

// ---------------------------------------------------------------- helpers
__device__ __forceinline__ uint32_t s2u(const void* p) {
    uint32_t a;
    asm("{ .reg .u64 t; cvta.to.shared.u64 t, %1; cvt.u32.u64 %0, t; }"
        : "=r"(a) : "l"(p));
    return a;
}
__device__ __forceinline__ float fast_ex2(float x) {
    float y; asm("ex2.approx.ftz.f32 %0, %1;" : "=f"(y) : "f"(x)); return y;
}
__device__ __forceinline__ void cpa16(uint32_t dst, const void* src) {
    asm volatile("cp.async.cg.shared.global [%0], [%1], 16;" :: "r"(dst), "l"(src));
}
#define CP_COMMIT() asm volatile("cp.async.commit_group;" ::: "memory")
#define CP_WAIT1()  asm volatile("cp.async.wait_group 1;" ::: "memory")

__device__ __forceinline__ void ldsm_x4(uint32_t &r0, uint32_t &r1, uint32_t &r2, uint32_t &r3,
                                        uint32_t addr) {
    asm volatile("ldmatrix.sync.aligned.m8n8.x4.shared.b16 {%0,%1,%2,%3}, [%4];"
                 : "=r"(r0), "=r"(r1), "=r"(r2), "=r"(r3) : "r"(addr));
}
__device__ __forceinline__ void imma_16832(int c[4],
                                           uint32_t a0, uint32_t a1, uint32_t a2, uint32_t a3,
                                           uint32_t b0, uint32_t b1) {
    asm volatile("mma.sync.aligned.m16n8k32.row.col.s32.s8.s8.s32 "
                 "{%0,%1,%2,%3}, {%4,%5,%6,%7}, {%8,%9}, {%0,%1,%2,%3};"
                 : "+r"(c[0]), "+r"(c[1]), "+r"(c[2]), "+r"(c[3])
                 : "r"(a0), "r"(a1), "r"(a2), "r"(a3), "r"(b0), "r"(b1));
}

// ---------------------------------------------------------------- labels
// Robust to int64 vs int32 delivery (labels are 0..15, so int64 => odd words 0).
__global__ void convert_labels_kernel(const int* __restrict__ raw) {
    int tid = threadIdx.x;
    int bad = 0;
    for (int i = tid; i < N_ROWS / 2; i += blockDim.x)
        if (raw[2 * i + 1] != 0) bad = 1;
    int any = __syncthreads_or(bad);
    if (any) { for (int r = tid; r < N_ROWS; r += blockDim.x) g_lab[r] = raw[r]; }
    else     { for (int r = tid; r < N_ROWS; r += blockDim.x) g_lab[r] = raw[2 * r]; }
}

// ---------------------------------------------------------------- prep
// Per row: norm + max|v|; quantize q = round(v * 127 / rowmax) (int8, exact dot);
// qs = rowmax / (127 * norm) * sqrt(log2e / T). Also zero accumulators.
__global__ void prep_kernel(const float* __restrict__ feat) {
    int r = blockIdx.x;
    int tid = threadIdx.x;   // 128 threads, 4 floats each
    float4 v = reinterpret_cast<const float4*>(feat + (size_t)r * D_DIM)[tid];
    float ss = v.x * v.x + v.y * v.y + v.z * v.z + v.w * v.w;
    float mx = fmaxf(fmaxf(fabsf(v.x), fabsf(v.y)), fmaxf(fabsf(v.z), fabsf(v.w)));
    #pragma unroll
    for (int o = 16; o; o >>= 1) {
        ss += __shfl_xor_sync(0xffffffffu, ss, o);
        mx = fmaxf(mx, __shfl_xor_sync(0xffffffffu, mx, o));
    }
    __shared__ float wsum[4], wmax[4];
    if ((tid & 31) == 0) { wsum[tid >> 5] = ss; wmax[tid >> 5] = mx; }
    __syncthreads();
    float tot = wsum[0] + wsum[1] + wsum[2] + wsum[3];
    float rmax = fmaxf(fmaxf(wmax[0], wmax[1]), fmaxf(wmax[2], wmax[3]));
    rmax = fmaxf(rmax, 1e-20f);
    float norm = fmaxf(sqrtf(tot), 1e-12f);

    float qsc = 127.0f / rmax;
    int ia = __float2int_rn(v.x * qsc);
    int ib = __float2int_rn(v.y * qsc);
    int ic = __float2int_rn(v.z * qsc);
    int id = __float2int_rn(v.w * qsc);
    uint32_t packed = (uint32_t)(ia & 0xFF) | ((uint32_t)(ib & 0xFF) << 8)
                    | ((uint32_t)(ic & 0xFF) << 16) | ((uint32_t)(id & 0xFF) << 24);
    reinterpret_cast<uint32_t*>(g_q + (size_t)r * D_DIM)[tid] = packed;

    if (tid == 0) {
        const float SQS = 4.539823f;  // sqrt(log2(e)/0.07)
        g_qs[r] = rmax / (127.0f * norm) * SQS;
        g_tot[r] = 0.f;
        g_same[r] = 0.f;
    }
}

// ---------------------------------------------------------------- main
// 128 CTAs = 64 row-tiles x 2 column halves. 8 warps: 4 rowGroups x 2 colGroups,
// each warp computes a 32x32 int8 GEMM block per chunk. cp.async double-buffers
// the 64-row B chunks; epilogue does exp + masked accumulation per element.
__device__ __forceinline__ void prefetch_chunk(uint32_t sm, int tid, int jbase, int buf) {
    uint32_t bdst = sm + SM_B + buf * BSZ;
    #pragma unroll
    for (int it = 0; it < 8; it++) {
        int i = tid + it * THREADS;
        int row = i >> 5, u = i & 31;
        cpa16(bdst + row * P + u * 16, g_q + (size_t)(jbase + row) * D_DIM + u * 16);
    }
    if (tid < 16)
        cpa16(sm + SM_L + buf * 256 + tid * 16,
              (const unsigned char*)g_lab + (size_t)jbase * 4 + tid * 16);
    else if (tid < 32)
        cpa16(sm + SM_Q + buf * 256 + (tid - 16) * 16,
              (const unsigned char*)g_qs + (size_t)jbase * 4 + (tid - 16) * 16);
}

__global__ void __launch_bounds__(THREADS, 1) contrastive_main_kernel() {
    extern __shared__ __align__(16) unsigned char smem[];
    uint32_t sm = s2u(smem);

    int tid  = threadIdx.x;
    int lane = tid & 31;
    int warp = tid >> 5;
    int rowGroup = warp >> 1;   // 0..3
    int colGroup = warp & 1;    // 0..1

    int rowBase  = (blockIdx.x >> 1) * ROW_TILE;
    int colStart = (blockIdx.x & 1) * COLS_PER_CTA;

    // A tile (group 0)
    #pragma unroll
    for (int it = 0; it < 16; it++) {
        int i = tid + it * THREADS;
        int row = i >> 5, u = i & 31;
        cpa16(sm + SM_A + row * P + u * 16, g_q + (size_t)(rowBase + row) * D_DIM + u * 16);
    }
    CP_COMMIT();
    prefetch_chunk(sm, tid, colStart, 0);          CP_COMMIT();
    prefetch_chunk(sm, tid, colStart + CHUNK, 1);  CP_COMMIT();

    int qr = lane >> 2;          // fragment row within 8
    int qc = (lane & 3) << 1;    // fragment col pair

    // per-thread row labels & quant scales: k = mt*2+h -> row = rg*32+mt*16+h*8+qr
    int rl[4]; float qrow[4];
    #pragma unroll
    for (int k = 0; k < 4; k++) {
        int row = rowBase + rowGroup * 32 + (k >> 1) * 16 + (k & 1) * 8 + qr;
        rl[k] = g_lab[row];
        qrow[k] = g_qs[row];
    }

    // ldmatrix base addresses (byte offsets identical to validated bf16 mapping)
    int m = lane >> 3, rim = lane & 7;
    uint32_t aBase[2], bOff[2];
    {
        int rowoff = (m & 1) * 8;
        int koff   = (m >> 1) * 16;
        #pragma unroll
        for (int mt = 0; mt < 2; mt++)
            aBase[mt] = sm + SM_A + (rowGroup * 32 + mt * 16 + rim + rowoff) * P + koff;
        int noff  = (m >> 1) * 8;
        int koff2 = (m & 1) * 16;
        #pragma unroll
        for (int nh = 0; nh < 2; nh++)
            bOff[nh] = (uint32_t)((colGroup * 32 + nh * 16 + rim + noff) * P + koff2);
    }

    CP_WAIT1();        // A + chunk0 resident
    __syncthreads();

    float tot[4] = {0.f, 0.f, 0.f, 0.f};
    float sme[4] = {0.f, 0.f, 0.f, 0.f};

    for (int chunk = 0; chunk < NCHUNKS; chunk++) {
        int buf = chunk & 1;
        int jbase = colStart + chunk * CHUNK;
        uint32_t bB = sm + SM_B + buf * BSZ;

        int acc[2][4][4];
        #pragma unroll
        for (int mt = 0; mt < 2; mt++)
            #pragma unroll
            for (int nf = 0; nf < 4; nf++)
                #pragma unroll
                for (int e = 0; e < 4; e++) acc[mt][nf][e] = 0;

        #pragma unroll 4
        for (int ks = 0; ks < D_DIM / 32; ks++) {     // 16 k-steps of 32 bytes
            uint32_t koffB = (uint32_t)ks * 32;
            uint32_t a[2][4];
            ldsm_x4(a[0][0], a[0][1], a[0][2], a[0][3], aBase[0] + koffB);
            ldsm_x4(a[1][0], a[1][1], a[1][2], a[1][3], aBase[1] + koffB);
            uint32_t b[4][2];
            {
                uint32_t r0, r1, r2, r3;
                ldsm_x4(r0, r1, r2, r3, bB + bOff[0] + koffB);
                b[0][0] = r0; b[0][1] = r1; b[1][0] = r2; b[1][1] = r3;
                ldsm_x4(r0, r1, r2, r3, bB + bOff[1] + koffB);
                b[2][0] = r0; b[2][1] = r1; b[3][0] = r2; b[3][1] = r3;
            }
            #pragma unroll
            for (int mt = 0; mt < 2; mt++)
                #pragma unroll
                for (int nf = 0; nf < 4; nf++)
                    imma_16832(acc[mt][nf], a[mt][0], a[mt][1], a[mt][2], a[mt][3],
                               b[nf][0], b[nf][1]);
        }

        // epilogue: e = ex2(i2f(idot) * qi * qj); exclude diagonal; split by label
        const int*   Ls = reinterpret_cast<const int*>(smem + SM_L + buf * 256);
        const float* Qs = reinterpret_cast<const float*>(smem + SM_Q + buf * 256);
        #pragma unroll
        for (int mt = 0; mt < 2; mt++) {
            #pragma unroll
            for (int nf = 0; nf < 4; nf++) {
                int cb  = colGroup * 32 + nf * 8 + qc;
                int j0  = jbase + cb;
                int lj0 = Ls[cb], lj1 = Ls[cb + 1];
                float qj0 = Qs[cb], qj1 = Qs[cb + 1];
                #pragma unroll
                for (int h = 0; h < 2; h++) {
                    int k = mt * 2 + h;
                    int gi = rowBase + rowGroup * 32 + mt * 16 + h * 8 + qr;
                    int li = rl[k];
                    float qi = qrow[k];
                    float e0 = fast_ex2((float)acc[mt][nf][2 * h]     * (qi * qj0));
                    float e1 = fast_ex2((float)acc[mt][nf][2 * h + 1] * (qi * qj1));
                    if (gi != j0)     { tot[k] += e0; if (li == lj0) sme[k] += e0; }
                    if (gi != j0 + 1) { tot[k] += e1; if (li == lj1) sme[k] += e1; }
                }
            }
        }

        __syncthreads();                        // all warps done reading buf
        if (chunk + 2 < NCHUNKS)
            prefetch_chunk(sm, tid, colStart + (chunk + 2) * CHUNK, buf);
        CP_COMMIT();                             // (possibly empty group)
        CP_WAIT1();                              // chunk+1 resident
        __syncthreads();
    }

    // quad-lane reduce (lanes 4q..4q+3 hold the same rows), then atomics
    #pragma unroll
    for (int k = 0; k < 4; k++) {
        float t = tot[k], s = sme[k];
        t += __shfl_xor_sync(0xffffffffu, t, 1);
        t += __shfl_xor_sync(0xffffffffu, t, 2);
        s += __shfl_xor_sync(0xffffffffu, s, 1);
        s += __shfl_xor_sync(0xffffffffu, s, 2);
        if ((lane & 3) == 0) {
            int row = rowBase + rowGroup * 32 + (k >> 1) * 16 + (k & 1) * 8 + qr;
            atomicAdd(&g_tot[row], t);
            atomicAdd(&g_same[row], s);
        }
    }
}

// ---------------------------------------------------------------- finalize
__global__ void finalize_kernel(float* __restrict__ out) {
    int tid = threadIdx.x;  // 1024
    float acc = 0.f;
    for (int r = tid; r < N_ROWS; r += 1024) {
        float t = g_tot[r];
        float p = g_same[r] + 1e-7f * t;
        acc += logf(p / t);
    }
    #pragma unroll
    for (int o = 16; o; o >>= 1) acc += __shfl_xor_sync(0xffffffffu, acc, o);
    __shared__ float ws[32];
    if ((tid & 31) == 0) ws[tid >> 5] = acc;
    __syncthreads();
    if (tid == 0) {
        float s = 0.f;
        #pragma unroll
        for (int w = 0; w < 32; w++) s += ws[w];
        float loss = -s / (float)N_ROWS;
        if (!isfinite(loss)) loss = 0.f;
        out[0] = loss;
    }
}

extern "C" void kernel_launch(void* const* d_in, const int* in_sizes, int n_in,
                              void* d_out, int out_size) {
    (void)in_sizes; (void)n_in; (void)out_size;
    const float* feat   = (const float*)d_in[0];
    const int*   labraw = (const int*)d_in[1];
    float* out = (float*)d_out;

    cudaFuncSetAttribute(contrastive_main_kernel,
                         cudaFuncAttributeMaxDynamicSharedMemorySize, SMEM_TOTAL);

    convert_labels_kernel<<<1, 256>>>(labraw);
    prep_kernel<<<N_ROWS, 128>>>(feat);
    contrastive_main_kernel<<<(N_ROWS / ROW_TILE) * COL_SPLIT, THREADS, SMEM_TOTAL>>>();
    finalize_kernel<<<1, 1024>>>(out);
}

// round 4
// speedup vs baseline: 3.2542x; 1.5952x over previous
#include <cuda_runtime.h>
#include <cuda_bf16.h>
#include <cstdint>

#define N_ROWS 8192
#define D_DIM  512
#define BLK 128
#define NBLK 64                         // 64 blocks of 128 rows
#define NTILES 2080                     // 64*65/2 upper-triangle tiles
#define GRID 139
#define TPC 15                          // tiles per CTA (139*15 = 2085 >= 2080)
#define P 528                           // int8 row pitch (conflict-free ldmatrix)
#define TILE_SM (BLK * P)               // 67584 bytes per block tile
#define THREADS 256

// smem layout (bytes)
#define SM_A  0                         // A block: 67584
#define SM_B  TILE_SM                   // 2 B blocks: 135168
#define SM_LB (SM_B + 2 * TILE_SM)      // 2 * 512 label bytes
#define SM_QB (SM_LB + 1024)            // 2 * 512 qscale bytes
#define SMEM_TOTAL (SM_QB + 1024)       // 204800

// static device scratch (cudaMalloc forbidden)
__device__ __align__(16) unsigned char g_q[N_ROWS * D_DIM];  // int8 rows
__device__ float g_qs[N_ROWS];
__device__ int   g_lab[N_ROWS];
__device__ float g_tot[N_ROWS];
__device__ float g_same[N_ROWS];

// ---------------------------------------------------------------- helpers
__device__ __forceinline__ uint32_t s2u(const void* p) {
    uint32_t a;
    asm("{ .reg .u64 t; cvta.to.shared.u64 t, %1; cvt.u32.u64 %0, t; }"
        : "=r"(a) : "l"(p));
    return a;
}
__device__ __forceinline__ float fast_ex2(float x) {
    float y; asm("ex2.approx.ftz.f32 %0, %1;" : "=f"(y) : "f"(x)); return y;
}
__device__ __forceinline__ float fast_lg2(float x) {
    float y; asm("lg2.approx.f32 %0, %1;" : "=f"(y) : "f"(x)); return y;
}
__device__ __forceinline__ void cpa16(uint32_t dst, const void* src) {
    asm volatile("cp.async.cg.shared.global [%0], [%1], 16;" :: "r"(dst), "l"(src));
}
#define CP_COMMIT() asm volatile("cp.async.commit_group;" ::: "memory")
#define CP_WAIT1()  asm volatile("cp.async.wait_group 1;" ::: "memory")

__device__ __forceinline__ void ldsm_x4(uint32_t &r0, uint32_t &r1, uint32_t &r2, uint32_t &r3,
                                        uint32_t addr) {
    asm volatile("ldmatrix.sync.aligned.m8n8.x4.shared.b16 {%0,%1,%2,%3}, [%4];"
                 : "=r"(r0), "=r"(r1), "=r"(r2), "=r"(r3) : "r"(addr));
}
__device__ __forceinline__ void imma_16832(int c[4],
                                           uint32_t a0, uint32_t a1, uint32_t a2, uint32_t a3,
                                           uint32_t b0, uint32_t b1) {
    asm volatile("mma.sync.aligned.m16n8k32.row.col.s32.s8.s8.s32 "
                 "{%0,%1,%2,%3}, {%4,%5,%6,%7}, {%8,%9}, {%0,%1,%2,%3};"
                 : "+r"(c[0]), "+r"(c[1]), "+r"(c[2]), "+r"(c[3])
                 : "r"(a0), "r"(a1), "r"(a2), "r"(a3), "r"(b0), "r"(b1));
}

// ---------------------------------------------------------------- labels
__global__ void convert_labels_kernel(const int* __restrict__ raw) {
    int tid = threadIdx.x;
    int bad = 0;
    for (int i = tid; i < N_ROWS / 2; i += blockDim.x)
        if (raw[2 * i + 1] != 0) bad = 1;
    int any = __syncthreads_or(bad);
    if (any) { for (int r = tid; r < N_ROWS; r += blockDim.x) g_lab[r] = raw[r]; }
    else     { for (int r = tid; r < N_ROWS; r += blockDim.x) g_lab[r] = raw[2 * r]; }
}

// ---------------------------------------------------------------- prep
__global__ void prep_kernel(const float* __restrict__ feat) {
    int r = blockIdx.x;
    int tid = threadIdx.x;   // 128 threads
    float4 v = reinterpret_cast<const float4*>(feat + (size_t)r * D_DIM)[tid];
    float ss = v.x * v.x + v.y * v.y + v.z * v.z + v.w * v.w;
    float mx = fmaxf(fmaxf(fabsf(v.x), fabsf(v.y)), fmaxf(fabsf(v.z), fabsf(v.w)));
    #pragma unroll
    for (int o = 16; o; o >>= 1) {
        ss += __shfl_xor_sync(0xffffffffu, ss, o);
        mx = fmaxf(mx, __shfl_xor_sync(0xffffffffu, mx, o));
    }
    __shared__ float wsum[4], wmax[4];
    if ((tid & 31) == 0) { wsum[tid >> 5] = ss; wmax[tid >> 5] = mx; }
    __syncthreads();
    float tot = wsum[0] + wsum[1] + wsum[2] + wsum[3];
    float rmax = fmaxf(fmaxf(wmax[0], wmax[1]), fmaxf(wmax[2], wmax[3]));
    rmax = fmaxf(rmax, 1e-20f);
    float norm = fmaxf(sqrtf(tot), 1e-12f);

    float qsc = 127.0f / rmax;
    int ia = __float2int_rn(v.x * qsc);
    int ib = __float2int_rn(v.y * qsc);
    int ic = __float2int_rn(v.z * qsc);
    int id = __float2int_rn(v.w * qsc);
    uint32_t packed = (uint32_t)(ia & 0xFF) | ((uint32_t)(ib & 0xFF) << 8)
                    | ((uint32_t)(ic & 0xFF) << 16) | ((uint32_t)(id & 0xFF) << 24);
    reinterpret_cast<uint32_t*>(g_q + (size_t)r * D_DIM)[tid] = packed;

    if (tid == 0) {
        const float SQS = 4.539823f;  // sqrt(log2(e)/0.07)
        g_qs[r] = rmax / (127.0f * norm) * SQS;
        g_tot[r] = 0.f;
        g_same[r] = 0.f;
    }
}

// ---------------------------------------------------------------- main
__device__ __forceinline__ void load_block(uint32_t dst, int blk, int tid) {
    const unsigned char* src = g_q + (size_t)blk * BLK * D_DIM;
    #pragma unroll
    for (int it = 0; it < 16; it++) {
        int idx = tid + it * THREADS;
        int row = idx >> 5, u = idx & 31;
        cpa16(dst + row * P + u * 16, src + row * D_DIM + u * 16);
    }
}
__device__ __forceinline__ void load_meta(uint32_t sm, int blk, int buf, int tid) {
    if (tid < 32)
        cpa16(sm + SM_LB + buf * 512 + tid * 16,
              (const unsigned char*)g_lab + (size_t)blk * 512 + tid * 16);
    else if (tid < 64)
        cpa16(sm + SM_QB + buf * 512 + (tid - 32) * 16,
              (const unsigned char*)g_qs + (size_t)blk * 512 + (tid - 32) * 16);
}

__global__ void __launch_bounds__(THREADS, 1) contrastive_main_kernel() {
    extern __shared__ __align__(16) unsigned char smem[];
    uint32_t sm = s2u(smem);

    int tid  = threadIdx.x;
    int lane = tid & 31;
    int warp = tid >> 5;
    int rg = warp >> 1;      // 0..3  (32-row group)
    int cg = warp & 1;       // 0..1  (64-col group)

    int t0 = blockIdx.x * TPC;
    int ntiles = NTILES - t0; if (ntiles > TPC) ntiles = TPC;
    if (ntiles <= 0) return;

    // decode first tile (row-major upper triangle: i fixed, j = i..63)
    int i = 0, rem = t0;
    while (rem >= NBLK - i) { rem -= NBLK - i; i++; }
    int j = i + rem;

    // initial loads: A(i), B(j) into buf 0
    load_block(sm + SM_A, i, tid);                  CP_COMMIT();
    load_block(sm + SM_B, j, tid); load_meta(sm, j, 0, tid); CP_COMMIT();

    // fragment addressing (validated int8/b16 ldmatrix mapping from R3)
    int qr = lane >> 2;
    int qc = (lane & 3) << 1;
    int m = lane >> 3, rim = lane & 7;
    uint32_t aBase[2], bOff[4];
    {
        int rowoff = (m & 1) * 8, koff = (m >> 1) * 16;
        #pragma unroll
        for (int mt = 0; mt < 2; mt++)
            aBase[mt] = sm + SM_A + (rg * 32 + mt * 16 + rim + rowoff) * P + koff;
        int noff = (m >> 1) * 8, koff2 = (m & 1) * 16;
        #pragma unroll
        for (int nh = 0; nh < 4; nh++)
            bOff[nh] = (uint32_t)((cg * 64 + nh * 16 + rim + noff) * P + koff2);
    }

    int a_loaded = i;
    int rowBase = i * BLK;
    int rl[4]; float qrow[4];
    #pragma unroll
    for (int k = 0; k < 4; k++) {
        int row = rowBase + rg * 32 + (k >> 1) * 16 + (k & 1) * 8 + qr;
        rl[k] = g_lab[row]; qrow[k] = g_qs[row];
    }
    float rtot[4] = {0.f, 0.f, 0.f, 0.f}, rsme[4] = {0.f, 0.f, 0.f, 0.f};

    #define FLUSH_ROWS() do { \
        _Pragma("unroll") for (int k = 0; k < 4; k++) { \
            float ft = rtot[k], fs = rsme[k]; \
            ft += __shfl_xor_sync(0xffffffffu, ft, 1); ft += __shfl_xor_sync(0xffffffffu, ft, 2); \
            fs += __shfl_xor_sync(0xffffffffu, fs, 1); fs += __shfl_xor_sync(0xffffffffu, fs, 2); \
            if ((lane & 3) == 0) { \
                int row_ = rowBase + rg * 32 + (k >> 1) * 16 + (k & 1) * 8 + qr; \
                atomicAdd(&g_tot[row_], ft); atomicAdd(&g_same[row_], fs); } \
            rtot[k] = 0.f; rsme[k] = 0.f; } \
    } while (0)

    for (int s = 0; s < ntiles; s++) {
        __syncthreads();   // all warps done reading smem from previous tile
        if (i != a_loaded) {
            load_block(sm + SM_A, i, tid); CP_COMMIT();
            a_loaded = i;
            FLUSH_ROWS();                       // old rowBase rows
            rowBase = i * BLK;
            #pragma unroll
            for (int k = 0; k < 4; k++) {
                int row = rowBase + rg * 32 + (k >> 1) * 16 + (k & 1) * 8 + qr;
                rl[k] = g_lab[row]; qrow[k] = g_qs[row];
            }
        }
        // prefetch next tile's B
        int nj = j + 1, ni = i;
        if (nj >= NBLK) { ni = i + 1; nj = ni; }
        if (s + 1 < ntiles) {
            load_block(sm + SM_B + ((s + 1) & 1) * TILE_SM, nj, tid);
            load_meta(sm, nj, (s + 1) & 1, tid);
        }
        CP_COMMIT();
        CP_WAIT1();        // current B (+A if reloaded) resident; next B still in flight
        __syncthreads();

        int buf = s & 1;
        uint32_t bB = sm + SM_B + buf * TILE_SM;
        int jbase = j * BLK;
        bool offd = (i != j);

        int acc[2][8][4];
        #pragma unroll
        for (int mt = 0; mt < 2; mt++)
            #pragma unroll
            for (int nf = 0; nf < 8; nf++)
                #pragma unroll
                for (int e = 0; e < 4; e++) acc[mt][nf][e] = 0;

        #pragma unroll 4
        for (int ks = 0; ks < D_DIM / 32; ks++) {
            uint32_t koffB = (uint32_t)ks * 32;
            uint32_t a[2][4];
            ldsm_x4(a[0][0], a[0][1], a[0][2], a[0][3], aBase[0] + koffB);
            ldsm_x4(a[1][0], a[1][1], a[1][2], a[1][3], aBase[1] + koffB);
            #pragma unroll
            for (int nh = 0; nh < 4; nh++) {
                uint32_t r0, r1, r2, r3;
                ldsm_x4(r0, r1, r2, r3, bB + bOff[nh] + koffB);
                imma_16832(acc[0][2 * nh],     a[0][0], a[0][1], a[0][2], a[0][3], r0, r1);
                imma_16832(acc[0][2 * nh + 1], a[0][0], a[0][1], a[0][2], a[0][3], r2, r3);
                imma_16832(acc[1][2 * nh],     a[1][0], a[1][1], a[1][2], a[1][3], r0, r1);
                imma_16832(acc[1][2 * nh + 1], a[1][0], a[1][1], a[1][2], a[1][3], r2, r3);
            }
        }

        // epilogue: exp + row-side accumulation (+ col-side for off-diag tiles)
        const int*   Ls = reinterpret_cast<const int*>(smem + SM_LB + buf * 512);
        const float* Qs = reinterpret_cast<const float*>(smem + SM_QB + buf * 512);
        float ctot[16], csme[16];
        #pragma unroll
        for (int v = 0; v < 16; v++) { ctot[v] = 0.f; csme[v] = 0.f; }

        #pragma unroll
        for (int mt = 0; mt < 2; mt++) {
            #pragma unroll
            for (int nf = 0; nf < 8; nf++) {
                int cb  = cg * 64 + nf * 8 + qc;
                int j0  = jbase + cb;
                int lj0 = Ls[cb], lj1 = Ls[cb + 1];
                float qj0 = Qs[cb], qj1 = Qs[cb + 1];
                #pragma unroll
                for (int h = 0; h < 2; h++) {
                    int k = mt * 2 + h;
                    int gi = rowBase + rg * 32 + mt * 16 + h * 8 + qr;
                    int li = rl[k]; float qi = qrow[k];
                    float e0 = fast_ex2((float)acc[mt][nf][2 * h]     * (qi * qj0));
                    float e1 = fast_ex2((float)acc[mt][nf][2 * h + 1] * (qi * qj1));
                    bool m0 = (li == lj0), m1 = (li == lj1);
                    if (gi != j0)     { rtot[k] += e0; if (m0) rsme[k] += e0; }
                    if (gi != j0 + 1) { rtot[k] += e1; if (m1) rsme[k] += e1; }
                    if (offd) {
                        ctot[2 * nf]     += e0; if (m0) csme[2 * nf]     += e0;
                        ctot[2 * nf + 1] += e1; if (m1) csme[2 * nf + 1] += e1;
                    }
                }
            }
        }

        if (offd) {
            // reduce col partials over the 8 lanes sharing each column (qr bits)
            #pragma unroll
            for (int v = 0; v < 16; v++) {
                float c1 = ctot[v], c2 = csme[v];
                c1 += __shfl_xor_sync(0xffffffffu, c1, 4);
                c1 += __shfl_xor_sync(0xffffffffu, c1, 8);
                c1 += __shfl_xor_sync(0xffffffffu, c1, 16);
                c2 += __shfl_xor_sync(0xffffffffu, c2, 4);
                c2 += __shfl_xor_sync(0xffffffffu, c2, 8);
                c2 += __shfl_xor_sync(0xffffffffu, c2, 16);
                ctot[v] = c1; csme[v] = c2;
            }
            if (lane < 4) {
                #pragma unroll
                for (int nf = 0; nf < 8; nf++) {
                    int c0 = jbase + cg * 64 + nf * 8 + qc;   // qc from lane 0..3
                    atomicAdd(&g_tot[c0],      ctot[2 * nf]);
                    atomicAdd(&g_tot[c0 + 1],  ctot[2 * nf + 1]);
                    atomicAdd(&g_same[c0],     csme[2 * nf]);
                    atomicAdd(&g_same[c0 + 1], csme[2 * nf + 1]);
                }
            }
        }

        // advance tile
        j++; if (j >= NBLK) { i++; j = i; }
    }
    FLUSH_ROWS();
    #undef FLUSH_ROWS
}

// ---------------------------------------------------------------- finalize
__global__ void finalize_kernel(float* __restrict__ out) {
    int tid = threadIdx.x;  // 1024
    float acc = 0.f;
    for (int r = tid; r < N_ROWS; r += 1024) {
        float t = g_tot[r];
        float p = g_same[r] + 1e-7f * t;
        acc += fast_lg2(p) - fast_lg2(t);
    }
    #pragma unroll
    for (int o = 16; o; o >>= 1) acc += __shfl_xor_sync(0xffffffffu, acc, o);
    __shared__ float ws[32];
    if ((tid & 31) == 0) ws[tid >> 5] = acc;
    __syncthreads();
    if (tid == 0) {
        float s = 0.f;
        #pragma unroll
        for (int w = 0; w < 32; w++) s += ws[w];
        float loss = -s * 0.69314718055994531f / (float)N_ROWS;
        if (!isfinite(loss)) loss = 0.f;
        out[0] = loss;
    }
}

extern "C" void kernel_launch(void* const* d_in, const int* in_sizes, int n_in,
                              void* d_out, int out_size) {
    (void)in_sizes; (void)n_in; (void)out_size;
    const float* feat   = (const float*)d_in[0];
    const int*   labraw = (const int*)d_in[1];
    float* out = (float*)d_out;

    cudaFuncSetAttribute(contrastive_main_kernel,
                         cudaFuncAttributeMaxDynamicSharedMemorySize, SMEM_TOTAL);

    convert_labels_kernel<<<1, 256>>>(labraw);
    prep_kernel<<<N_ROWS, 128>>>(feat);
    contrastive_main_kernel<<<GRID, THREADS, SMEM_TOTAL>>>();
    finalize_kernel<<<1, 1024>>>(out);
}